// round 7
// baseline (speedup 1.0000x reference)
#include <cuda_runtime.h>
#include <math.h>
typedef unsigned long long ull;

#define NTH 256
#define TST 1024
#define BATCH 1024
#define EPSF 1e-8f

#define W10O 0
#define W20O 9088
#define W11O 18176
#define W21O 34688
#define WOUTO 51200
#define BAo 51584
#define BBo 51648
#define ACT0 51712   // [quad2][70][4], quad stride 280
#define SCR 52272    // [quad2][128][4], quad stride 512
#define PLf 53296    // 2304 ull partial scratch
#define XBo 57904
#define NBo 57952
#define SMF 57960    // 231,840 B

__device__ __forceinline__ ull pack2(float lo, float hi){ull r;asm("mov.b64 %0,{%1,%2};":"=l"(r):"f"(lo),"f"(hi));return r;}
__device__ __forceinline__ void unpack2(ull v,float&lo,float&hi){asm("mov.b64 {%0,%1},%2;":"=f"(lo),"=f"(hi):"l"(v));}
__device__ __forceinline__ void ffma2(ull&d,ull a,ull b){asm("fma.rn.f32x2 %0,%1,%2,%0;":"+l"(d):"l"(a),"l"(b));}
__device__ __forceinline__ ull addx2(ull a,ull b){ull r;asm("add.rn.f32x2 %0,%1,%2;":"=l"(r):"l"(a),"l"(b));return r;}
__device__ __forceinline__ ull mulx2(ull a,ull b){ull r;asm("mul.rn.f32x2 %0,%1,%2;":"=l"(r):"l"(a),"l"(b));return r;}

__global__ void __launch_bounds__(NTH, 1)
lmsc_kernel(const float* __restrict__ x, const float* __restrict__ initF,
            const float* __restrict__ w10,const float* __restrict__ b10,
            const float* __restrict__ w20,const float* __restrict__ b20,
            const float* __restrict__ w11,const float* __restrict__ b11,
            const float* __restrict__ w21,const float* __restrict__ b21,
            const float* __restrict__ w12,const float* __restrict__ b12,
            const float* __restrict__ w22,const float* __restrict__ b22,
            const float* __restrict__ wa, const float* __restrict__ ba,
            const float* __restrict__ wb, const float* __restrict__ bb,
            const float* __restrict__ wout,float* __restrict__ out)
{
    extern __shared__ float sm[];
    ull* PLu = (ull*)(sm + PLf);
    const int tid = threadIdx.x;
    const int b0 = blockIdx.x * 8;
    const int j = tid & 127;
    const int cb = tid >> 7;       // L0: row-quad; L1/L2: k-half

    for (int idx = tid; idx < 70*128; idx += NTH) {
        int k = idx >> 7, jj = idx & 127;
        sm[W10O + jj*71 + k] = w10[idx];
        sm[W20O + jj*71 + k] = w20[idx];
    }
    for (int idx = tid; idx < 128*128; idx += NTH) {
        int k = idx >> 7, jj = idx & 127;
        sm[W11O + jj*129 + k] = w11[idx];
        sm[W21O + jj*129 + k] = w21[idx];
    }
    for (int idx = tid; idx < 384; idx += NTH) sm[WOUTO + idx] = wout[idx];
    if (tid < 64) { sm[BAo + tid] = ba[tid]; sm[BBo + tid] = bb[tid]; }
    for (int idx = tid; idx < 512; idx += NTH) {
        int r = idx >> 6, jj = idx & 63;
        sm[ACT0 + (r>>2)*280 + (6+jj)*4 + (r&3)] = initF[(b0+r)*66 + 2 + jj];
    }

    const ull b0m1 = pack2(b10[j], b10[j]);
    const ull b0m2 = pack2(b20[j], b20[j]);
    const ull b1m1 = cb ? 0ULL : pack2(b11[j], b11[j]);
    const ull b1m2 = cb ? 0ULL : pack2(b21[j], b21[j]);
    const ull b2m1 = cb ? 0ULL : pack2(b12[j], b12[j]);
    const ull b2m2 = cb ? 0ULL : pack2(b22[j], b22[j]);

    float wl2a[64], wl2b[64];
#pragma unroll
    for (int i = 0; i < 64; i++) {
        wl2a[i] = w12[(cb*64+i)*128 + j];
        wl2b[i] = w22[(cb*64+i)*128 + j];
    }
    const int jh = tid & 63, chd = tid >> 6;   // heads 4-way k-split over 128
    float wha[32], whb[32];
#pragma unroll
    for (int i = 0; i < 32; i++) {
        wha[i] = wa[(chd*32+i)*64 + jh];
        whb[i] = wb[(chd*32+i)*64 + jh];
    }

    const int xr = tid / 6, xd = tid - 6*xr;
    float xc = 0.f;
    if (tid < 48) sm[XBo + tid] = x[((size_t)(b0+xr)*TST)*6 + xd];
    __syncthreads();
    if (tid < 8) {
        float s = 0.f;
#pragma unroll
        for (int d = 0; d < 6; d++){ float v = sm[XBo + tid*6 + d]; s = fmaf(v,v,s); }
        float nrm = sqrtf(s); sm[NBo + tid] = nrm;
        float inv = 1.0f/(nrm + EPSF);
#pragma unroll
        for (int d = 0; d < 6; d++)
            sm[ACT0 + (tid>>2)*280 + d*4 + (tid&3)] = sm[XBo + tid*6 + d]*inv;
    }
    if (tid < 48) xc = x[((size_t)(b0+xr)*TST + 1)*6 + xd];

    float* outs = out;
    float* alph = out + (size_t)BATCH*TST*6;

#pragma unroll 1
    for (int t = 0; t < TST; t++) {
        __syncthreads();                       // A: x/h ready

        {   // L0: thread (j, quad cb), K=70, fused tanh-gate -> SCR
            const float* w1p = sm + W10O + j*71;
            const float* w2p = sm + W20O + j*71;
            const float* ap  = sm + ACT0 + cb*280;
            ull a1x=b0m1, a1y=b0m1, a2x=b0m2, a2y=b0m2;
#pragma unroll 14
            for (int k = 0; k < 70; k++) {
                ulonglong2 q = *(const ulonglong2*)(ap + k*4);
                ull w1 = pack2(w1p[k], w1p[k]);
                ull w2 = pack2(w2p[k], w2p[k]);
                ffma2(a1x,q.x,w1); ffma2(a1y,q.y,w1);
                ffma2(a2x,q.x,w2); ffma2(a2y,q.y,w2);
            }
            float p0,p1,p2,p3,q0,q1,q2,q3;
            unpack2(a1x,p0,p1); unpack2(a1y,p2,p3);
            unpack2(a2x,q0,q1); unpack2(a2y,q2,q3);
            *(float4*)(sm + SCR + cb*512 + j*4) = make_float4(
                tanhf(p0)*tanhf(q0), tanhf(p1)*tanhf(q1),
                tanhf(p2)*tanhf(q2), tanhf(p3)*tanhf(q3));
        }
        __syncthreads();                       // B

        {   // L1 partial: thread (j, khalf cb), all 8 rows
            const float* w1p = sm + W11O + j*129 + cb*64;
            const float* w2p = sm + W21O + j*129 + cb*64;
            const float* apA = sm + SCR + cb*256;
            const float* apB = sm + SCR + 512 + cb*256;
            ull p0=b1m1,p1=b1m1,p2=b1m1,p3=b1m1,q0=b1m2,q1=b1m2,q2=b1m2,q3=b1m2;
#pragma unroll 16
            for (int i = 0; i < 64; i++) {
                ulonglong2 qa = *(const ulonglong2*)(apA + i*4);
                ulonglong2 qb = *(const ulonglong2*)(apB + i*4);
                ull w1 = pack2(w1p[i], w1p[i]);
                ull w2 = pack2(w2p[i], w2p[i]);
                ffma2(p0,qa.x,w1); ffma2(p1,qa.y,w1); ffma2(p2,qb.x,w1); ffma2(p3,qb.y,w1);
                ffma2(q0,qa.x,w2); ffma2(q1,qa.y,w2); ffma2(q2,qb.x,w2); ffma2(q3,qb.y,w2);
            }
            ull* pp = PLu + cb*1152 + j*9;
            pp[0]=p0;pp[1]=p1;pp[2]=p2;pp[3]=p3;pp[4]=q0;pp[5]=q1;pp[6]=q2;pp[7]=q3;
        }
        __syncthreads();                       // C

        {   // L1 combine: thread (jc, quad h): g = tanh(x1)*tanh(x2)
            const int jc = tid >> 1, h = tid & 1;
            const ull* c0 = PLu + jc*9;
            const ull* c1 = PLu + 1152 + jc*9;
            ull u10 = addx2(c0[2*h],   c1[2*h]);
            ull u11 = addx2(c0[2*h+1], c1[2*h+1]);
            ull u20 = addx2(c0[4+2*h],   c1[4+2*h]);
            ull u21 = addx2(c0[4+2*h+1], c1[4+2*h+1]);
            float p0,p1,p2,p3,q0,q1,q2,q3;
            unpack2(u10,p0,p1); unpack2(u11,p2,p3);
            unpack2(u20,q0,q1); unpack2(u21,q2,q3);
            *(float4*)(sm + SCR + h*512 + jc*4) = make_float4(
                tanhf(p0)*tanhf(q0), tanhf(p1)*tanhf(q1),
                tanhf(p2)*tanhf(q2), tanhf(p3)*tanhf(q3));
        }
        __syncthreads();                       // D

        {   // L2 partial: thread (j, khalf cb), register weights
            const float* apA = sm + SCR + cb*256;
            const float* apB = sm + SCR + 512 + cb*256;
            ull p0=b2m1,p1=b2m1,p2=b2m1,p3=b2m1,q0=b2m2,q1=b2m2,q2=b2m2,q3=b2m2;
#pragma unroll 16
            for (int i = 0; i < 64; i++) {
                ulonglong2 qa = *(const ulonglong2*)(apA + i*4);
                ulonglong2 qb = *(const ulonglong2*)(apB + i*4);
                ull w1 = pack2(wl2a[i], wl2a[i]);
                ull w2 = pack2(wl2b[i], wl2b[i]);
                ffma2(p0,qa.x,w1); ffma2(p1,qa.y,w1); ffma2(p2,qb.x,w1); ffma2(p3,qb.y,w1);
                ffma2(q0,qa.x,w2); ffma2(q1,qa.y,w2); ffma2(q2,qb.x,w2); ffma2(q3,qb.y,w2);
            }
            ull* pp = PLu + cb*1152 + j*9;
            pp[0]=p0;pp[1]=p1;pp[2]=p2;pp[3]=p3;pp[4]=q0;pp[5]=q1;pp[6]=q2;pp[7]=q3;
        }
        __syncthreads();                       // E

        {   // L2 combine: g = tanh(x1*x2)
            const int jc = tid >> 1, h = tid & 1;
            const ull* c0 = PLu + jc*9;
            const ull* c1 = PLu + 1152 + jc*9;
            ull u10 = addx2(c0[2*h],   c1[2*h]);
            ull u11 = addx2(c0[2*h+1], c1[2*h+1]);
            ull u20 = addx2(c0[4+2*h],   c1[4+2*h]);
            ull u21 = addx2(c0[4+2*h+1], c1[4+2*h+1]);
            ull v0 = mulx2(u10,u20), v1 = mulx2(u11,u21);
            float g0,g1,g2,g3;
            unpack2(v0,g0,g1); unpack2(v1,g2,g3);
            *(float4*)(sm + SCR + h*512 + jc*4) = make_float4(
                tanhf(g0), tanhf(g1), tanhf(g2), tanhf(g3));
        }
        __syncthreads();                       // F

        {   // heads partial: thread (jh, kquarter chd), both wa/wb, 8 rows
            const float* apA = sm + SCR + chd*128;
            const float* apB = sm + SCR + 512 + chd*128;
            ull pa0=0,pa1=0,pa2=0,pa3=0,pb0=0,pb1=0,pb2=0,pb3=0;
#pragma unroll 16
            for (int i = 0; i < 32; i++) {
                ulonglong2 qa = *(const ulonglong2*)(apA + i*4);
                ulonglong2 qb = *(const ulonglong2*)(apB + i*4);
                ull w1 = pack2(wha[i], wha[i]);
                ull w2 = pack2(whb[i], whb[i]);
                ffma2(pa0,qa.x,w1); ffma2(pa1,qa.y,w1); ffma2(pa2,qb.x,w1); ffma2(pa3,qb.y,w1);
                ffma2(pb0,qa.x,w2); ffma2(pb1,qa.y,w2); ffma2(pb2,qb.x,w2); ffma2(pb3,qb.y,w2);
            }
            ull* pp = PLu + chd*576 + jh*9;
            pp[0]=pa0;pp[1]=pa1;pp[2]=pa2;pp[3]=pa3;pp[4]=pb0;pp[5]=pb1;pp[6]=pb2;pp[7]=pb3;
        }
        __syncthreads();                       // G

        {   // heads combine + h update + alpha out; stage x(t+1)
            const int jj = tid & 63, i = tid >> 6;     // rows 2i, 2i+1
            ull ua = addx2(addx2(PLu[jj*9+i],        PLu[576+jj*9+i]),
                           addx2(PLu[1152+jj*9+i],   PLu[1728+jj*9+i]));
            ull ub = addx2(addx2(PLu[jj*9+4+i],      PLu[576+jj*9+4+i]),
                           addx2(PLu[1152+jj*9+4+i], PLu[1728+jj*9+4+i]));
            float pa0,pa1,pb0,pb1;
            unpack2(ua,pa0,pa1); unpack2(ub,pb0,pb1);
            const float bav = sm[BAo+jj], bbv = sm[BBo+jj];
            const int q = i >> 1, s0 = (2*i) & 3;
            const int hoff = ACT0 + q*280 + (6+jj)*4 + s0;
            float al0 = expf(pa0 + bav), al1 = expf(pa1 + bav);
            float be0 = tanhf(pb0 + bbv), be1 = tanhf(pb1 + bbv);
            float h0 = sm[hoff], h1 = sm[hoff+1];
            float hn0 = fmaf(expf(-al0*sm[NBo+2*i]),   h0-be0, be0);
            float hn1 = fmaf(expf(-al1*sm[NBo+2*i+1]), h1-be1, be1);
            *(ull*)(sm + hoff) = pack2(hn0, hn1);
            alph[((size_t)(b0+2*i)*TST + t)*64 + jj]   = al0;
            alph[((size_t)(b0+2*i+1)*TST + t)*64 + jj] = al1;
            if (tid < 48 && t+1 < TST) sm[XBo + tid] = xc;
        }
        __syncthreads();                       // H

        if (tid < 48) {   // outs = h @ wout; prefetch x(t+2)
            const int r = tid/6, o = tid - 6*r;
            const int base = ACT0 + (r>>2)*280 + (r&3);
            float acc = 0.f;
#pragma unroll
            for (int k = 0; k < 64; k++)
                acc = fmaf(sm[base + (6+k)*4], sm[WOUTO + k*6 + o], acc);
            outs[((size_t)(b0+r)*TST + t)*6 + o] = acc;
            if (t+2 < TST) xc = x[((size_t)(b0+xr)*TST + (t+2))*6 + xd];
        }
        if (tid < 8 && t+1 < TST) {   // norm + xn for t+1
            float s = 0.f;
#pragma unroll
            for (int d = 0; d < 6; d++){ float v = sm[XBo + tid*6 + d]; s = fmaf(v,v,s); }
            float nrm = sqrtf(s); sm[NBo + tid] = nrm;
            float inv = 1.0f/(nrm + EPSF);
#pragma unroll
            for (int d = 0; d < 6; d++)
                sm[ACT0 + (tid>>2)*280 + d*4 + (tid&3)] = sm[XBo + tid*6 + d]*inv;
        }
    }
}

extern "C" void kernel_launch(void* const* d_in, const int* in_sizes, int n_in,
                              void* d_out, int out_size)
{
    const float* x    =(const float*)d_in[0];  const float* initF=(const float*)d_in[1];
    const float* w10  =(const float*)d_in[2];  const float* b10  =(const float*)d_in[3];
    const float* w20  =(const float*)d_in[4];  const float* b20  =(const float*)d_in[5];
    const float* w11  =(const float*)d_in[6];  const float* b11  =(const float*)d_in[7];
    const float* w21  =(const float*)d_in[8];  const float* b21  =(const float*)d_in[9];
    const float* w12  =(const float*)d_in[10]; const float* b12  =(const float*)d_in[11];
    const float* w22  =(const float*)d_in[12]; const float* b22  =(const float*)d_in[13];
    const float* wa   =(const float*)d_in[14]; const float* ba   =(const float*)d_in[15];
    const float* wb   =(const float*)d_in[16]; const float* bb   =(const float*)d_in[17];
    const float* wout =(const float*)d_in[18];
    float* out = (float*)d_out;

    const int smem_bytes = SMF * 4;
    cudaFuncSetAttribute(lmsc_kernel, cudaFuncAttributeMaxDynamicSharedMemorySize, smem_bytes);
    lmsc_kernel<<<BATCH/8, NTH, smem_bytes>>>(x, initF, w10,b10,w20,b20, w11,b11,w21,b21,
                                              w12,b12,w22,b22, wa,ba,wb,bb, wout, out);
}